// round 5
// baseline (speedup 1.0000x reference)
#include <cuda_runtime.h>
#include <math.h>

#define BB      8
#define LSEQ    4096
#define DIMC    384
#define NDEPTH  6
#define NSTATE  16
#define NCONV   4
#define DINNER  768
#define DTRANK  24
#define HIDF    768
#define MTOK    (BB*LSEQ)        // 32768
#define DBLW    (DTRANK + 2*NSTATE)   // 56

// ---------------- scratch (static device globals; no allocation) ----------------
__device__ float g_x  [MTOK*DIMC];        // residual stream
__device__ float g_xn [MTOK*DIMC];        // layernorm output
__device__ float g_xz [MTOK*2*DINNER];    // in_proj output (xi | z)
__device__ float g_xi [MTOK*DINNER];      // conv+silu output
__device__ float g_dbl[MTOK*DBLW];        // xproj output (dt_r | B | C)
__device__ float g_dt [MTOK*DINNER];      // softplus(dt)
__device__ float g_y  [MTOK*DINNER];      // scan output / gated / ff hidden

// ---------------- helpers ----------------
__device__ __forceinline__ float siluf(float v) {
    return v / (1.0f + expf(-v));
}
__device__ __forceinline__ float softplusf(float v) {
    // stable logaddexp(v, 0)
    return (v >= 0.0f) ? (v + log1pf(expf(-v))) : log1pf(expf(v));
}
__device__ __forceinline__ float geluf(float v) {
    // jax.nn.gelu approximate=True (tanh)
    float c = 0.7978845608028654f * (v + 0.044715f * v * v * v);
    return 0.5f * v * (1.0f + tanhf(c));
}

// ---------------- elementwise: x = x + pos_emb ----------------
__global__ void add_pos_kernel(const float* __restrict__ x,
                               const float* __restrict__ pos,
                               float* __restrict__ out) {
    int idx = blockIdx.x * blockDim.x + threadIdx.x;   // over MTOK*DIMC/4
    if (idx >= MTOK * DIMC / 4) return;
    int m  = idx / (DIMC / 4);
    int c4 = idx % (DIMC / 4);
    int l  = m & (LSEQ - 1);
    float4 xv = ((const float4*)x)[idx];
    float4 pv = ((const float4*)pos)[l * (DIMC / 4) + c4];
    xv.x += pv.x; xv.y += pv.y; xv.z += pv.z; xv.w += pv.w;
    ((float4*)out)[idx] = xv;
}

// ---------------- layernorm over DIMC=384 (one warp per token) ----------------
__global__ void ln_kernel(const float* __restrict__ x, float* __restrict__ o,
                          const float* __restrict__ s, const float* __restrict__ bb) {
    int gwarp = (blockIdx.x * blockDim.x + threadIdx.x) >> 5;
    int lane  = threadIdx.x & 31;
    if (gwarp >= MTOK) return;
    const float* xp = x + (size_t)gwarp * DIMC;
    float4 v0 = *(const float4*)(xp + lane * 4);
    float4 v1 = *(const float4*)(xp + 128 + lane * 4);
    float4 v2 = *(const float4*)(xp + 256 + lane * 4);
    float sum = v0.x + v0.y + v0.z + v0.w
              + v1.x + v1.y + v1.z + v1.w
              + v2.x + v2.y + v2.z + v2.w;
    #pragma unroll
    for (int off = 16; off >= 1; off >>= 1) sum += __shfl_xor_sync(0xffffffffu, sum, off);
    float mean = sum * (1.0f / DIMC);
    float q = 0.0f;
    #define QACC(t) { float d_ = (t) - mean; q = fmaf(d_, d_, q); }
    QACC(v0.x) QACC(v0.y) QACC(v0.z) QACC(v0.w)
    QACC(v1.x) QACC(v1.y) QACC(v1.z) QACC(v1.w)
    QACC(v2.x) QACC(v2.y) QACC(v2.z) QACC(v2.w)
    #undef QACC
    #pragma unroll
    for (int off = 16; off >= 1; off >>= 1) q += __shfl_xor_sync(0xffffffffu, q, off);
    float rstd = rsqrtf(q * (1.0f / DIMC) + 1e-5f);

    float4 s0 = *(const float4*)(s + lane * 4);
    float4 s1 = *(const float4*)(s + 128 + lane * 4);
    float4 s2 = *(const float4*)(s + 256 + lane * 4);
    float4 b0 = *(const float4*)(bb + lane * 4);
    float4 b1 = *(const float4*)(bb + 128 + lane * 4);
    float4 b2 = *(const float4*)(bb + 256 + lane * 4);
    float* op = o + (size_t)gwarp * DIMC;
    float4 r;
    r.x = (v0.x - mean) * rstd * s0.x + b0.x;
    r.y = (v0.y - mean) * rstd * s0.y + b0.y;
    r.z = (v0.z - mean) * rstd * s0.z + b0.z;
    r.w = (v0.w - mean) * rstd * s0.w + b0.w;
    *(float4*)(op + lane * 4) = r;
    r.x = (v1.x - mean) * rstd * s1.x + b1.x;
    r.y = (v1.y - mean) * rstd * s1.y + b1.y;
    r.z = (v1.z - mean) * rstd * s1.z + b1.z;
    r.w = (v1.w - mean) * rstd * s1.w + b1.w;
    *(float4*)(op + 128 + lane * 4) = r;
    r.x = (v2.x - mean) * rstd * s2.x + b2.x;
    r.y = (v2.y - mean) * rstd * s2.y + b2.y;
    r.z = (v2.z - mean) * rstd * s2.z + b2.z;
    r.w = (v2.w - mean) * rstd * s2.w + b2.w;
    *(float4*)(op + 256 + lane * 4) = r;
}

// ---------------- generic TN SGEMM: C[M,N] = A[M,K] @ W[N,K]^T, fused epilogue ----------------
// EPI: 0=store, 1=softplus(v+bias), 2=gelu(v+bias), 3=C+=v, 4=C+=v+bias
#define BM 128
#define BN 128
#define BKK 8

template <int EPI>
__global__ void __launch_bounds__(256)
sgemm_tn(const float* __restrict__ A, const float* __restrict__ W,
         float* __restrict__ C, const float* __restrict__ bias,
         int M, int N, int K, int lda, int ldw, int ldc) {
    __shared__ float As[BKK][BM + 4];
    __shared__ float Bs[BKK][BN + 4];

    int m0 = blockIdx.y * BM;
    int n0 = blockIdx.x * BN;
    int tid = threadIdx.x;
    int lrow = tid >> 1;            // 0..127
    int lcol = (tid & 1) * 4;       // 0 or 4
    int tx = tid & 15, ty = tid >> 4;

    float acc[8][8];
    #pragma unroll
    for (int i = 0; i < 8; i++)
        #pragma unroll
        for (int j = 0; j < 8; j++) acc[i][j] = 0.0f;

    // first prefetch
    float4 ra = *(const float4*)(A + (size_t)(m0 + lrow) * lda + lcol);
    float4 rb;
    {
        int n = n0 + lrow;
        rb = (n < N) ? *(const float4*)(W + (size_t)n * ldw + lcol)
                     : make_float4(0.f, 0.f, 0.f, 0.f);
    }

    for (int k0 = 0; k0 < K; k0 += BKK) {
        As[lcol + 0][lrow] = ra.x;
        As[lcol + 1][lrow] = ra.y;
        As[lcol + 2][lrow] = ra.z;
        As[lcol + 3][lrow] = ra.w;
        Bs[lcol + 0][lrow] = rb.x;
        Bs[lcol + 1][lrow] = rb.y;
        Bs[lcol + 2][lrow] = rb.z;
        Bs[lcol + 3][lrow] = rb.w;
        __syncthreads();

        if (k0 + BKK < K) {
            ra = *(const float4*)(A + (size_t)(m0 + lrow) * lda + (k0 + BKK) + lcol);
            int n = n0 + lrow;
            rb = (n < N) ? *(const float4*)(W + (size_t)n * ldw + (k0 + BKK) + lcol)
                         : make_float4(0.f, 0.f, 0.f, 0.f);
        }

        #pragma unroll
        for (int k = 0; k < BKK; k++) {
            float4 a0 = *(const float4*)&As[k][ty * 4];
            float4 a1 = *(const float4*)&As[k][ty * 4 + 64];
            float4 b0 = *(const float4*)&Bs[k][tx * 4];
            float4 b1 = *(const float4*)&Bs[k][tx * 4 + 64];
            float av[8] = {a0.x, a0.y, a0.z, a0.w, a1.x, a1.y, a1.z, a1.w};
            float bv[8] = {b0.x, b0.y, b0.z, b0.w, b1.x, b1.y, b1.z, b1.w};
            #pragma unroll
            for (int ii = 0; ii < 8; ii++)
                #pragma unroll
                for (int jj = 0; jj < 8; jj++)
                    acc[ii][jj] = fmaf(av[ii], bv[jj], acc[ii][jj]);
        }
        __syncthreads();
    }

    // epilogue
    #pragma unroll
    for (int ii = 0; ii < 8; ii++) {
        int r = m0 + ty * 4 + ((ii < 4) ? ii : 64 + ii - 4);
        float* crow = C + (size_t)r * ldc;
        #pragma unroll
        for (int jj = 0; jj < 8; jj++) {
            int c = n0 + tx * 4 + ((jj < 4) ? jj : 64 + jj - 4);
            if (c >= N) continue;
            float v = acc[ii][jj];
            if (EPI == 0) {
                crow[c] = v;
            } else if (EPI == 1) {
                crow[c] = softplusf(v + bias[c]);
            } else if (EPI == 2) {
                crow[c] = geluf(v + bias[c]);
            } else if (EPI == 3) {
                crow[c] += v;
            } else {
                crow[c] += v + bias[c];
            }
        }
    }
}

// ---------------- causal depthwise conv (DCONV=4) + silu ----------------
__global__ void conv_silu_kernel(const float* __restrict__ xz, float* __restrict__ xi,
                                 const float* __restrict__ w, const float* __restrict__ cb) {
    int idx = blockIdx.x * blockDim.x + threadIdx.x;   // over MTOK*DINNER/4
    if (idx >= MTOK * DINNER / 4) return;
    int m  = idx / (DINNER / 4);
    int d4 = (idx % (DINNER / 4)) * 4;
    int l  = m & (LSEQ - 1);
    float4 cbv = *(const float4*)(cb + d4);
    float4 acc = cbv;
    const float* base = xz + (size_t)m * (2 * DINNER) + d4;
    #pragma unroll
    for (int k = 0; k < NCONV; k++) {
        int dl = l - (NCONV - 1) + k;
        if (dl >= 0) {
            float4 xv = *(const float4*)(base + (size_t)(k - (NCONV - 1)) * (2 * DINNER));
            acc.x = fmaf(xv.x, w[(d4 + 0) * NCONV + k], acc.x);
            acc.y = fmaf(xv.y, w[(d4 + 1) * NCONV + k], acc.y);
            acc.z = fmaf(xv.z, w[(d4 + 2) * NCONV + k], acc.z);
            acc.w = fmaf(xv.w, w[(d4 + 3) * NCONV + k], acc.w);
        }
    }
    acc.x = siluf(acc.x);
    acc.y = siluf(acc.y);
    acc.z = siluf(acc.z);
    acc.w = siluf(acc.w);
    *(float4*)(xi + (size_t)m * DINNER + d4) = acc;
}

// ---------------- selective scan ----------------
// grid (BB, DINNER/16), block 256 = 16 d x 16 s
__global__ void __launch_bounds__(256)
scan_kernel(const float* __restrict__ xi, const float* __restrict__ dt,
            const float* __restrict__ dbl, const float* __restrict__ A_log,
            const float* __restrict__ Dp, float* __restrict__ y) {
    int b    = blockIdx.x;
    int dblk = blockIdx.y;
    int tid  = threadIdx.x;
    int dl   = tid >> 4;
    int s    = tid & 15;
    int d    = dblk * 16 + dl;

    float aL2 = -expf(A_log[d * NSTATE + s]) * 1.4426950408889634f;  // log2(e)
    float Dd  = Dp[d];
    float h = 0.0f;

    const float* dt_p = dt  + (size_t)b * LSEQ * DINNER + d;
    const float* u_p  = xi  + (size_t)b * LSEQ * DINNER + d;
    const float* bc_p = dbl + (size_t)b * LSEQ * DBLW;
    float*       y_p  = y   + (size_t)b * LSEQ * DINNER + d;

    #pragma unroll 4
    for (int t = 0; t < LSEQ; t++) {
        float dtv = dt_p[(size_t)t * DINNER];
        float uv  = u_p[(size_t)t * DINNER];
        float Bv  = bc_p[(size_t)t * DBLW + DTRANK + s];
        float Cv  = bc_p[(size_t)t * DBLW + DTRANK + NSTATE + s];
        float dA  = exp2f(dtv * aL2);
        h = fmaf(h, dA, (dtv * uv) * Bv);
        float p = h * Cv;
        p += __shfl_xor_sync(0xffffffffu, p, 8);
        p += __shfl_xor_sync(0xffffffffu, p, 4);
        p += __shfl_xor_sync(0xffffffffu, p, 2);
        p += __shfl_xor_sync(0xffffffffu, p, 1);
        if (s == 0) y_p[(size_t)t * DINNER] = fmaf(uv, Dd, p);
    }
}

// ---------------- y *= silu(z)  (z = xz[:, DINNER:]) ----------------
__global__ void gmul_kernel(float* __restrict__ y, const float* __restrict__ xz) {
    int idx = blockIdx.x * blockDim.x + threadIdx.x;   // over MTOK*DINNER/4
    if (idx >= MTOK * DINNER / 4) return;
    int m  = idx / (DINNER / 4);
    int d4 = (idx % (DINNER / 4)) * 4;
    float4 yv = ((float4*)y)[idx];
    float4 zv = *(const float4*)(xz + (size_t)m * (2 * DINNER) + DINNER + d4);
    yv.x *= siluf(zv.x);
    yv.y *= siluf(zv.y);
    yv.z *= siluf(zv.z);
    yv.w *= siluf(zv.w);
    ((float4*)y)[idx] = yv;
}

// ---------------- host launcher ----------------
static inline int cdiv(int a, int b) { return (a + b - 1) / b; }

extern "C" void kernel_launch(void* const* d_in, const int* in_sizes, int n_in,
                              void* d_out, int out_size) {
    const float* x_in     = (const float*)d_in[0];
    const float* pos      = (const float*)d_in[1];
    const float* ln1_s    = (const float*)d_in[2];
    const float* ln1_b    = (const float*)d_in[3];
    const float* in_w     = (const float*)d_in[4];
    const float* conv_w   = (const float*)d_in[5];
    const float* conv_b   = (const float*)d_in[6];
    const float* xproj_w  = (const float*)d_in[7];
    const float* dtproj_w = (const float*)d_in[8];
    const float* dtproj_b = (const float*)d_in[9];
    const float* A_log    = (const float*)d_in[10];
    const float* Dp       = (const float*)d_in[11];
    const float* out_w    = (const float*)d_in[12];
    const float* ff_ln_s  = (const float*)d_in[13];
    const float* ff_ln_b  = (const float*)d_in[14];
    const float* ff_w1    = (const float*)d_in[15];
    const float* ff_b1    = (const float*)d_in[16];
    const float* ff_w2    = (const float*)d_in[17];
    const float* ff_b2    = (const float*)d_in[18];
    const float* lno_s    = (const float*)d_in[19];
    const float* lno_b    = (const float*)d_in[20];

    float *bx, *bxn, *bxz, *bxi, *bdbl, *bdt, *by;
    cudaGetSymbolAddress((void**)&bx,   g_x);
    cudaGetSymbolAddress((void**)&bxn,  g_xn);
    cudaGetSymbolAddress((void**)&bxz,  g_xz);
    cudaGetSymbolAddress((void**)&bxi,  g_xi);
    cudaGetSymbolAddress((void**)&bdbl, g_dbl);
    cudaGetSymbolAddress((void**)&bdt,  g_dt);
    cudaGetSymbolAddress((void**)&by,   g_y);

    const int EW_BLK = 256;
    int ew_inner = cdiv(MTOK * DINNER / 4, EW_BLK);
    int ew_dim   = cdiv(MTOK * DIMC / 4, EW_BLK);

    // x = x + pos_emb
    add_pos_kernel<<<ew_dim, EW_BLK>>>(x_in, pos, bx);

    for (int i = 0; i < NDEPTH; i++) {
        // ---- mamba block ----
        ln_kernel<<<MTOK / 8, 256>>>(bx, bxn, ln1_s + (size_t)i * DIMC, ln1_b + (size_t)i * DIMC);

        // xz = xn @ in_w^T  [M,1536]
        sgemm_tn<0><<<dim3(cdiv(2 * DINNER, BN), MTOK / BM), 256>>>(
            bxn, in_w + (size_t)i * 2 * DINNER * DIMC, bxz, nullptr,
            MTOK, 2 * DINNER, DIMC, DIMC, DIMC, 2 * DINNER);

        // xi = silu(conv1d(xz[:, :768]))
        conv_silu_kernel<<<ew_inner, EW_BLK>>>(
            bxz, bxi, conv_w + (size_t)i * DINNER * NCONV, conv_b + (size_t)i * DINNER);

        // dbl = xi @ xproj_w^T  [M,56]
        sgemm_tn<0><<<dim3(cdiv(DBLW, BN), MTOK / BM), 256>>>(
            bxi, xproj_w + (size_t)i * DBLW * DINNER, bdbl, nullptr,
            MTOK, DBLW, DINNER, DINNER, DINNER, DBLW);

        // dt = softplus(dbl[:, :24] @ dtproj_w^T + dtproj_b)  [M,768]
        sgemm_tn<1><<<dim3(cdiv(DINNER, BN), MTOK / BM), 256>>>(
            bdbl, dtproj_w + (size_t)i * DINNER * DTRANK, bdt,
            dtproj_b + (size_t)i * DINNER,
            MTOK, DINNER, DTRANK, DBLW, DTRANK, DINNER);

        // selective scan -> y
        scan_kernel<<<dim3(BB, DINNER / 16), 256>>>(
            bxi, bdt, bdbl, A_log + (size_t)i * DINNER * NSTATE,
            Dp + (size_t)i * DINNER, by);

        // y *= silu(z)
        gmul_kernel<<<ew_inner, EW_BLK>>>(by, bxz);

        // x += y @ out_w^T
        sgemm_tn<3><<<dim3(cdiv(DIMC, BN), MTOK / BM), 256>>>(
            by, out_w + (size_t)i * DIMC * DINNER, bx, nullptr,
            MTOK, DIMC, DINNER, DINNER, DINNER, DIMC);

        // ---- feed-forward block ----
        ln_kernel<<<MTOK / 8, 256>>>(bx, bxn, ff_ln_s + (size_t)i * DIMC, ff_ln_b + (size_t)i * DIMC);

        // h = gelu(xn @ ff_w1^T + b1)
        sgemm_tn<2><<<dim3(cdiv(HIDF, BN), MTOK / BM), 256>>>(
            bxn, ff_w1 + (size_t)i * HIDF * DIMC, by, ff_b1 + (size_t)i * HIDF,
            MTOK, HIDF, DIMC, DIMC, DIMC, HIDF);

        // x += h @ ff_w2^T + b2
        sgemm_tn<4><<<dim3(cdiv(DIMC, BN), MTOK / BM), 256>>>(
            by, ff_w2 + (size_t)i * DIMC * HIDF, bx, ff_b2 + (size_t)i * DIMC,
            MTOK, DIMC, HIDF, HIDF, HIDF, DIMC);
    }

    // final layernorm -> d_out
    ln_kernel<<<MTOK / 8, 256>>>(bx, (float*)d_out, lno_s, lno_b);
}